// round 9
// baseline (speedup 1.0000x reference)
#include <cuda_runtime.h>
#include <math.h>

#define VOLD   256
#define NGAUSS 4000
// Tile shape 4 x 8 x 16 (x,y,z): 32 (x,y) rows -> 32 lanes; 64B z-row stores.
#define TSX 4
#define TSY 8
#define TSZ 16
#define NTX 64
#define NTY 32
#define NTZ 16
#define NTILES (NTX * NTY * NTZ)      // 32768
#define CAP    32
#define SLICE  28                     // wx[4] wy[8] wz[16]

// ---------------------------------------------------------------------------
// Static device scratch. Zeroed at module load; gather self-cleans g_cnt each
// launch, so the invariant holds across correctness run, capture, and replays.
// g_ids needs no cleaning: only entries [0, cnt) are ever read.
// ---------------------------------------------------------------------------
__device__ int g_cnt[NTILES];
__device__ int g_ids[NTILES * CAP];   // 4 MB

// ---------------------------------------------------------------------------
// Kernel 1: binning only. Block per Gaussian; threads 0..2 compute the
// per-axis tile bbox (no exps), then thread-per-pair atomic + id store.
// ---------------------------------------------------------------------------
__global__ __launch_bounds__(128) void prep_kernel(
    const float* __restrict__ centers,
    const float* __restrict__ sigmas)
{
    const int g = blockIdx.x;
    const int t = threadIdx.x;

    __shared__ int s_tmin[3], s_tn[3];

    if (t < 3) {
        const float sig = sigmas[g];
        const float cn  = centers[3 * g + t];
        const float cv  = cn * 255.0f;
        const float cut = 3.0f * sig * 255.0f;

        const float minf = fmaxf(cv - cut, 0.0f);
        const float maxf = fminf(cv + cut, 255.0f);
        const int   mini = (int)floorf(minf);
        const int   maxi = min((int)floorf(maxf) + 1, VOLD);   // exclusive

        const int shf  = (t == 0) ? 2 : ((t == 1) ? 3 : 4);
        const int tmin = mini >> shf;
        const int tmax = (maxi - 1) >> shf;
        s_tmin[t] = tmin;
        s_tn[t]   = tmax - tmin + 1;
    }
    __syncthreads();

    const int nx = s_tn[0], ny = s_tn[1], nz = s_tn[2];
    const int x0 = s_tmin[0], y0 = s_tmin[1], z0 = s_tmin[2];
    const int total = nx * ny * nz;

    for (int i = t; i < total; i += 128) {
        const int iz = i % nz;
        const int r  = i / nz;
        const int iy = r % ny;
        const int ix = r / ny;
        const int tile = ((x0 + ix) * NTY + (y0 + iy)) * NTZ + (z0 + iz);

        const int slot = atomicAdd(&g_cnt[tile], 1);
        if (slot < CAP) g_ids[tile * CAP + slot] = g;
    }
}

// ---------------------------------------------------------------------------
// Kernel 2: gather, warp per tile (8 tiles per 256-thread block). Each warp
// reads its id list, COMPUTES the 28-float separable slice per pair in-place
// (lanes 0..27, one weight each), then runs the register FMA accumulation and
// writes 4 contiguous float4 per lane. No slice intermediate in global memory.
// ---------------------------------------------------------------------------
__global__ __launch_bounds__(256) void gather_kernel(
    const float* __restrict__ centers,
    const float* __restrict__ sigmas,
    const float* __restrict__ intens,
    float* __restrict__ vol)
{
    const int warp = threadIdx.x >> 5;
    const int lane = threadIdx.x & 31;
    const int tile = blockIdx.x * 8 + warp;

    __shared__ __align__(16) float sh[8][CAP * SLICE];   // 28 KB

    const int cnt = min(g_cnt[tile], CAP);
    int myid = 0;
    if (lane < cnt) myid = g_ids[tile * CAP + lane];
    if (lane == 0) g_cnt[tile] = 0;       // restore invariant for next launch

    const int tzi = tile & (NTZ - 1);
    const int tyi = (tile >> 4) & (NTY - 1);
    const int txi = tile >> 9;

    // Per-lane slice role: lanes 0-3 wx, 4-11 wy, 12-27 wz (28-31 idle)
    const int axis = (lane < 4) ? 0 : ((lane < 12) ? 1 : 2);
    const int o    = lane - ((lane < 4) ? 0 : ((lane < 12) ? 4 : 12));
    const int tb   = (axis == 0) ? txi * TSX : ((axis == 1) ? tyi * TSY : tzi * TSZ);
    const int idxv = tb + o;
    const float pos = (float)idxv * (1.0f / 255.0f);

    float* __restrict__ swp = sh[warp];

    for (int p = 0; p < cnt; ++p) {
        const int gid = __shfl_sync(0xffffffffu, myid, p);
        const float sig = sigmas[gid];
        const float c   = centers[3 * gid + axis];
        const float I   = intens[gid];

        const float cv  = c * 255.0f;
        const float cut = 3.0f * sig * 255.0f;
        const float minf = fmaxf(cv - cut, 0.0f);
        const float maxf = fminf(cv + cut, 255.0f);
        const int   mini = (int)floorf(minf);
        const int   maxi = min((int)floorf(maxf) + 1, VOLD);

        float w = 0.0f;
        if (idxv >= mini && idxv < maxi) {
            const float d = pos - c;
            const float a = __fdividef(0.5f, sig * sig);
            w = __expf(-d * d * a);
        }
        if (axis == 0) w *= I;
        if (lane < 28) swp[p * SLICE + lane] = w;
    }
    __syncwarp();

    // FMA accumulation: lane = (x,y) row, 16-voxel z row in registers.
    const int x = lane >> 3;
    const int y = lane & 7;

    float acc[16];
#pragma unroll
    for (int i = 0; i < 16; ++i) acc[i] = 0.f;

#pragma unroll 4
    for (int p = 0; p < cnt; ++p) {
        const float* s = swp + p * SLICE;
        const float f = s[x] * s[4 + y];
#pragma unroll
        for (int q = 0; q < 4; ++q) {
            const float4 wz = *(const float4*)(s + 12 + 4 * q);
            acc[4*q+0] = fmaf(f, wz.x, acc[4*q+0]);
            acc[4*q+1] = fmaf(f, wz.y, acc[4*q+1]);
            acc[4*q+2] = fmaf(f, wz.z, acc[4*q+2]);
            acc[4*q+3] = fmaf(f, wz.w, acc[4*q+3]);
        }
    }

    float* out = vol + ((size_t)(txi * TSX + x) * VOLD + (tyi * TSY + y)) * VOLD
                     + tzi * TSZ;
#pragma unroll
    for (int q = 0; q < 4; ++q)
        *(float4*)(out + 4 * q) =
            make_float4(acc[4*q+0], acc[4*q+1], acc[4*q+2], acc[4*q+3]);
}

// ---------------------------------------------------------------------------
extern "C" void kernel_launch(void* const* d_in, const int* in_sizes, int n_in,
                              void* d_out, int out_size) {
    const float* centers = (const float*)d_in[0];
    const float* sigmas  = (const float*)d_in[1];
    const float* intens  = (const float*)d_in[2];
    float* vol = (float*)d_out;

    prep_kernel<<<NGAUSS, 128>>>(centers, sigmas);
    gather_kernel<<<NTILES / 8, 256>>>(centers, sigmas, intens, vol);
}

// round 11
// speedup vs baseline: 1.1889x; 1.1889x over previous
#include <cuda_runtime.h>
#include <math.h>

#define VOLD   256
#define NGAUSS 4000
// Tile shape 8 x 8 x 16 (x,y,z): 64 (x,y) rows -> 2 rows/lane; 64B z-row stores.
#define TSX 8
#define TSY 8
#define TSZ 16
#define NTX 32
#define NTY 32
#define NTZ 16
#define NTILES (NTX * NTY * NTZ)      // 16384
#define CAP    32
#define SLICE  32                     // wx[8] wy[8] wz[16]

// ---------------------------------------------------------------------------
// Static device scratch. Zeroed at module load; gather self-cleans g_cnt each
// launch, so the invariant holds across correctness run, capture, and replays.
// g_ids needs no cleaning: only entries [0, cnt) are ever read.
// ---------------------------------------------------------------------------
__device__ int g_cnt[NTILES];
__device__ int g_ids[NTILES * CAP];   // 2 MB

// ---------------------------------------------------------------------------
// Kernel 1: binning only. Block per Gaussian; threads 0..2 compute the
// per-axis tile bbox (no exps), then thread-per-pair atomic + id store.
// ---------------------------------------------------------------------------
__global__ __launch_bounds__(128) void prep_kernel(
    const float* __restrict__ centers,
    const float* __restrict__ sigmas)
{
    const int g = blockIdx.x;
    const int t = threadIdx.x;

    __shared__ int s_tmin[3], s_tn[3];

    if (t < 3) {
        const float sig = sigmas[g];
        const float cn  = centers[3 * g + t];
        const float cv  = cn * 255.0f;
        const float cut = 3.0f * sig * 255.0f;

        const float minf = fmaxf(cv - cut, 0.0f);
        const float maxf = fminf(cv + cut, 255.0f);
        const int   mini = (int)floorf(minf);
        const int   maxi = min((int)floorf(maxf) + 1, VOLD);   // exclusive

        const int shf  = (t == 2) ? 4 : 3;
        const int tmin = mini >> shf;
        const int tmax = (maxi - 1) >> shf;
        s_tmin[t] = tmin;
        s_tn[t]   = tmax - tmin + 1;
    }
    __syncthreads();

    const int nx = s_tn[0], ny = s_tn[1], nz = s_tn[2];
    const int x0 = s_tmin[0], y0 = s_tmin[1], z0 = s_tmin[2];
    const int total = nx * ny * nz;          // <= ~48

    for (int i = t; i < total; i += 128) {
        const int iz = i % nz;
        const int r  = i / nz;
        const int iy = r % ny;
        const int ix = r / ny;
        const int tile = ((x0 + ix) * NTY + (y0 + iy)) * NTZ + (z0 + iz);

        const int slot = atomicAdd(&g_cnt[tile], 1);
        if (slot < CAP) g_ids[tile * CAP + slot] = g;
    }
}

// ---------------------------------------------------------------------------
// Kernel 2: gather, warp per 8x8x16 tile (8 tiles per 256-thread block).
// Lane p preloads Gaussian p's parameters; the weight loop is pure
// shuffle+ALU+exp (no memory ops). Warp writes each pair's 32-float slice to
// shared, then each lane accumulates two 16-voxel z rows in registers and
// writes 8 contiguous float4. No slice intermediate in global memory.
// ---------------------------------------------------------------------------
__global__ __launch_bounds__(256, 3) void gather_kernel(
    const float* __restrict__ centers,
    const float* __restrict__ sigmas,
    const float* __restrict__ intens,
    float* __restrict__ vol)
{
    const int warp = threadIdx.x >> 5;
    const int lane = threadIdx.x & 31;
    const int tile = blockIdx.x * 8 + warp;

    __shared__ __align__(16) float sh[8][CAP * SLICE];   // 32 KB

    const int cnt = min(g_cnt[tile], CAP);

    // Per-lane parameter preload for Gaussian #lane of this tile (full MLP).
    float m_a = 0.f, m_cut = 0.f, m_I = 0.f, m_c0 = 0.f, m_c1 = 0.f, m_c2 = 0.f;
    if (lane < cnt) {
        const int gid = g_ids[tile * CAP + lane];
        const float sig = sigmas[gid];
        m_a   = __fdividef(0.5f, sig * sig);
        m_cut = 3.0f * sig * 255.0f;
        m_I   = intens[gid];
        m_c0  = centers[3 * gid + 0];
        m_c1  = centers[3 * gid + 1];
        m_c2  = centers[3 * gid + 2];
    }
    if (lane == 0) g_cnt[tile] = 0;       // restore invariant for next launch

    const int tzi = tile & (NTZ - 1);
    const int tyi = (tile >> 4) & (NTY - 1);
    const int txi = tile >> 9;

    // Per-lane slice role: lanes 0-7 wx, 8-15 wy, 16-31 wz
    const int axis = min(lane >> 3, 2);
    const int o    = lane - (axis << 3);
    const int tb   = (axis == 0) ? txi * TSX : ((axis == 1) ? tyi * TSY : tzi * TSZ);
    const int idxv = tb + o;
    const float pos = (float)idxv * (1.0f / 255.0f);

    float* __restrict__ swp = sh[warp];

#pragma unroll 2
    for (int p = 0; p < cnt; ++p) {
        const float a   = __shfl_sync(0xffffffffu, m_a,   p);
        const float cut = __shfl_sync(0xffffffffu, m_cut, p);
        const float I   = __shfl_sync(0xffffffffu, m_I,   p);
        const float c0  = __shfl_sync(0xffffffffu, m_c0,  p);
        const float c1  = __shfl_sync(0xffffffffu, m_c1,  p);
        const float c2  = __shfl_sync(0xffffffffu, m_c2,  p);
        const float c   = (axis == 0) ? c0 : ((axis == 1) ? c1 : c2);

        const float cv  = c * 255.0f;
        const float minf = fmaxf(cv - cut, 0.0f);
        const float maxf = fminf(cv + cut, 255.0f);
        const int   mini = (int)floorf(minf);
        const int   maxi = min((int)floorf(maxf) + 1, VOLD);

        float w = 0.0f;
        if (idxv >= mini && idxv < maxi) {
            const float d = pos - c;
            w = __expf(-d * d * a);
        }
        if (axis == 0) w *= I;
        swp[p * SLICE + lane] = w;
    }
    __syncwarp();

    // FMA accumulation: lane owns rows (x0,y) and (x0+4,y), 16 z each.
    const int x0 = lane >> 3;             // 0..3
    const int y  = lane & 7;

    float a0[16], a1[16];
#pragma unroll
    for (int i = 0; i < 16; ++i) { a0[i] = 0.f; a1[i] = 0.f; }

#pragma unroll 2
    for (int p = 0; p < cnt; ++p) {
        const float* s = swp + p * SLICE;
        const float wy = s[8 + y];
        const float f0 = s[x0] * wy;
        const float f1 = s[x0 + 4] * wy;
#pragma unroll
        for (int q = 0; q < 4; ++q) {
            const float4 wz = *(const float4*)(s + 16 + 4 * q);
            a0[4*q+0] = fmaf(f0, wz.x, a0[4*q+0]);
            a0[4*q+1] = fmaf(f0, wz.y, a0[4*q+1]);
            a0[4*q+2] = fmaf(f0, wz.z, a0[4*q+2]);
            a0[4*q+3] = fmaf(f0, wz.w, a0[4*q+3]);
            a1[4*q+0] = fmaf(f1, wz.x, a1[4*q+0]);
            a1[4*q+1] = fmaf(f1, wz.y, a1[4*q+1]);
            a1[4*q+2] = fmaf(f1, wz.z, a1[4*q+2]);
            a1[4*q+3] = fmaf(f1, wz.w, a1[4*q+3]);
        }
    }

    float* out0 = vol + ((size_t)(txi * TSX + x0) * VOLD + (tyi * TSY + y)) * VOLD
                      + tzi * TSZ;
    float* out1 = out0 + (size_t)4 * VOLD * VOLD;     // x0 + 4
#pragma unroll
    for (int q = 0; q < 4; ++q) {
        *(float4*)(out0 + 4 * q) = make_float4(a0[4*q+0], a0[4*q+1], a0[4*q+2], a0[4*q+3]);
        *(float4*)(out1 + 4 * q) = make_float4(a1[4*q+0], a1[4*q+1], a1[4*q+2], a1[4*q+3]);
    }
}

// ---------------------------------------------------------------------------
extern "C" void kernel_launch(void* const* d_in, const int* in_sizes, int n_in,
                              void* d_out, int out_size) {
    const float* centers = (const float*)d_in[0];
    const float* sigmas  = (const float*)d_in[1];
    const float* intens  = (const float*)d_in[2];
    float* vol = (float*)d_out;

    prep_kernel<<<NGAUSS, 128>>>(centers, sigmas);
    gather_kernel<<<NTILES / 8, 256>>>(centers, sigmas, intens, vol);
}